// round 2
// baseline (speedup 1.0000x reference)
#include <cuda_runtime.h>
#include <cstdint>

// Problem constants
#define B_    64
#define T_    1024
#define D_    300
#define H_    512
#define G_    (4*H_)     // 2048 gate columns
#define KTOT  (D_ + H_)  // 812
#define NCTA  128        // each CTA owns 4 h-columns -> 16 gate columns
#define NTHR  256
#define HC    4
#define GC    16

// Scratch (no cudaMalloc allowed): double-buffered h (col-major [col][b]) + mot partials
__device__ float    g_h[2][H_ * B_];
__device__ float    g_mot[H_ * B_];
__device__ unsigned g_bar_count = 0;
__device__ unsigned g_bar_gen   = 0;

// ---- Blackwell packed fp32 helpers (FFMA2 path: 2x fp32 FMA throughput) ----
__device__ __forceinline__ void ffma2(uint64_t& d, uint64_t a, uint64_t b) {
    asm volatile("fma.rn.f32x2 %0, %1, %2, %0;" : "+l"(d) : "l"(a), "l"(b));
}
__device__ __forceinline__ uint64_t pack_dup(float x) {
    uint64_t r; asm("mov.b64 %0, {%1, %1};" : "=l"(r) : "f"(x)); return r;
}
__device__ __forceinline__ uint64_t pack2(float x, float y) {
    uint64_t r; asm("mov.b64 %0, {%1, %2};" : "=l"(r) : "f"(x), "f"(y)); return r;
}
__device__ __forceinline__ float2 unpack2(uint64_t v) {
    float2 f; asm("mov.b64 {%0, %1}, %2;" : "=f"(f.x), "=f"(f.y) : "l"(v)); return f;
}
__device__ __forceinline__ void lds_v2u64(uint64_t& a, uint64_t& b, unsigned addr) {
    asm volatile("ld.shared.v2.u64 {%0, %1}, [%2];" : "=l"(a), "=l"(b) : "r"(addr));
}
__device__ __forceinline__ float sigm(float x) { return 1.0f / (1.0f + __expf(-x)); }
__device__ __forceinline__ float tanh_f(float x) { return 2.0f * sigm(2.0f * x) - 1.0f; }

// Persistent LSTM scan. Grid = 128 CTAs (all co-resident on 148 SMs -> spin barrier safe).
// CTA cc owns h columns [cc*4, cc*4+4) i.e. gate columns {g*512 + cc*4 + j}.
// Thread map: warp w owns rows m in [8w, 8w+8); lane = (ng<<3)|m7; thread owns gate g=ng,
// h-col jj=0..3 accumulators for one row m, and LSTM state c for (m, hcol=cc*4+ng).
extern __shared__ float smem_dyn[];
__global__ void __launch_bounds__(NTHR, 1)
lstm_scan_kernel(const float* __restrict__ essays,
                 const float* __restrict__ W_lstm,
                 const float* __restrict__ b_lstm)
{
    float* Wsm  = smem_dyn;            // [KTOT][16]
    float* Apan = smem_dyn + KTOT*GC;  // [64][64] panel / gate-exchange buffer

    const int tid  = threadIdx.x;
    const int cc   = blockIdx.x;
    const int w    = tid >> 5;
    const int lane = tid & 31;
    const int m    = w*8 + (lane & 7);   // batch row (B=64)
    const int ng   = lane >> 3;          // gate index 0..3 (i,j,f,o)
    const int q0   = ng*4;               // local W-slice column group

    // Cache W slice in SMEM: Wsm[k][q], q=(g,jj): col = g*512 + cc*4 + jj
    for (int idx = tid; idx < KTOT*GC; idx += NTHR) {
        int k = idx >> 4, q = idx & 15;
        int col = (q >> 2) * H_ + cc*HC + (q & 3);
        Wsm[idx] = W_lstm[(size_t)k * G_ + col];
    }

    const int colb = ng*H_ + cc*HC;
    const uint64_t bias01 = pack2(b_lstm[colb+0], b_lstm[colb+1]);
    const uint64_t bias23 = pack2(b_lstm[colb+2], b_lstm[colb+3]);

    const int hcol = cc*HC + ng;
    g_h[0][hcol*B_ + m] = 0.0f;            // h_{-1} = 0 (must re-zero every launch)

    const unsigned wbase = (unsigned)__cvta_generic_to_shared(Wsm);

    __shared__ unsigned s_gen;
    if (tid == 0) s_gen = *((volatile unsigned*)&g_bar_gen);
    __threadfence();                        // publish h zero (all threads)
    __syncthreads();
    unsigned target = s_gen;

    // arrive #0 (zeroed h published)
    if (tid == 0) {
        unsigned a = atomicAdd(&g_bar_count, 1);
        if (a == NCTA-1) { *((volatile unsigned*)&g_bar_count) = 0; __threadfence(); atomicAdd(&g_bar_gen, 1); }
    }

    float    c_st = 0.0f, hsum = 0.0f;
    uint64_t acc01 = bias01, acc23 = bias23;

    const float* xrow = essays + (size_t)m * (T_ * D_);

    // X-phase: gates += x_t @ Wx  (independent of h -> overlaps barrier latency)
    auto do_x = [&](int t) {
        const float4* xp = (const float4*)(xrow + (size_t)t * D_);
        #pragma unroll 3
        for (int kv = 0; kv < D_/4; kv++) {
            float4 a4 = xp[kv];
            unsigned wa = wbase + (unsigned)((kv*4)*GC + q0) * 4u;
            uint64_t w01, w23, a2;
            lds_v2u64(w01, w23, wa      ); a2 = pack_dup(a4.x); ffma2(acc01, w01, a2); ffma2(acc23, w23, a2);
            lds_v2u64(w01, w23, wa +  64); a2 = pack_dup(a4.y); ffma2(acc01, w01, a2); ffma2(acc23, w23, a2);
            lds_v2u64(w01, w23, wa + 128); a2 = pack_dup(a4.z); ffma2(acc01, w01, a2); ffma2(acc23, w23, a2);
            lds_v2u64(w01, w23, wa + 192); a2 = pack_dup(a4.w); ffma2(acc01, w01, a2); ffma2(acc23, w23, a2);
        }
    };

    do_x(0);

    for (int t = 0; t < T_; t++) {
        // Wait for h_{t-1} to be globally visible
        target += 1;
        if (tid == 0) {
            while (*((volatile unsigned*)&g_bar_gen) != target) { __nanosleep(32); }
            __threadfence();   // CCTL.IVALL: invalidate stale L1 lines of h
        }
        __syncthreads();

        // H-phase: gates += h_{t-1} @ Wh, staged through SMEM in 64-k panels
        const float* hb = g_h[t & 1];
        #pragma unroll 1
        for (int kp = 0; kp < H_; kp += 64) {
            const float4* src = (const float4*)(hb + kp*B_);
            float4*       dst = (float4*)Apan;
            #pragma unroll
            for (int r = 0; r < 4; r++) dst[tid + r*NTHR] = src[tid + r*NTHR];
            __syncthreads();
            unsigned wa = wbase + (unsigned)((D_ + kp)*GC + q0) * 4u;
            #pragma unroll 8
            for (int k = 0; k < 64; k++) {
                uint64_t a2 = pack_dup(Apan[k*B_ + m]);
                uint64_t w01, w23;
                lds_v2u64(w01, w23, wa + (unsigned)k*64u);
                ffma2(acc01, w01, a2); ffma2(acc23, w23, a2);
            }
            __syncthreads();
        }

        // Gate exchange: thread owns (g=ng, jj=0..3); needs (g=0..3, jj=ng)
        float2 v01 = unpack2(acc01), v23 = unpack2(acc23);
        Apan[(q0+0)*B_ + m] = v01.x;
        Apan[(q0+1)*B_ + m] = v01.y;
        Apan[(q0+2)*B_ + m] = v23.x;
        Apan[(q0+3)*B_ + m] = v23.y;
        __syncthreads();
        float gi = Apan[(0*4 + ng)*B_ + m];
        float gj = Apan[(1*4 + ng)*B_ + m];
        float gf = Apan[(2*4 + ng)*B_ + m];
        float go = Apan[(3*4 + ng)*B_ + m];

        float nc = c_st * sigm(gf + 1.0f) + sigm(gi) * tanh_f(gj);
        float nh = tanh_f(nc) * sigm(go);
        c_st = nc;
        hsum += nh;
        g_h[(t+1) & 1][hcol*B_ + m] = nh;

        __threadfence();      // publish h_t (every thread, before CTA arrival)
        __syncthreads();

        if (t < T_ - 1) {
            if (tid == 0) {
                unsigned a = atomicAdd(&g_bar_count, 1);
                if (a == NCTA-1) { *((volatile unsigned*)&g_bar_count) = 0; __threadfence(); atomicAdd(&g_bar_gen, 1); }
            }
            acc01 = bias01; acc23 = bias23;
            do_x(t + 1);      // overlap next step's x-projection with barrier skew
        }
    }

    g_mot[hcol*B_ + m] = hsum * (1.0f / (float)T_);
}

__global__ void finalize_kernel(const float* __restrict__ W_dense,
                                const float* __restrict__ b_dense,
                                float* __restrict__ out)
{
    int b = threadIdx.x;          // 64 threads
    float acc = b_dense[0];
    #pragma unroll 8
    for (int col = 0; col < H_; col++)
        acc += g_mot[col*B_ + b] * W_dense[col];
    out[b] = 1.0f / (1.0f + expf(-acc));
}

extern "C" void kernel_launch(void* const* d_in, const int* in_sizes, int n_in,
                              void* d_out, int out_size)
{
    const float* essays  = (const float*)d_in[0];
    const float* W_lstm  = (const float*)d_in[1];
    const float* b_lstm  = (const float*)d_in[2];
    const float* W_dense = (const float*)d_in[3];
    const float* b_dense = (const float*)d_in[4];
    float* out = (float*)d_out;

    const int smem_bytes = (KTOT*GC + 64*B_) * (int)sizeof(float); // 51968 + 16384 = 68352
    cudaFuncSetAttribute(lstm_scan_kernel,
                         cudaFuncAttributeMaxDynamicSharedMemorySize, smem_bytes);

    lstm_scan_kernel<<<NCTA, NTHR, smem_bytes>>>(essays, W_lstm, b_lstm);
    finalize_kernel<<<1, B_>>>(W_dense, b_dense, out);
}

// round 3
// speedup vs baseline: 1.1292x; 1.1292x over previous
#include <cuda_runtime.h>
#include <cstdint>

// Problem constants
#define B_    64
#define T_    1024
#define D_    300
#define H_    512
#define G_    (4*H_)     // 2048 gate columns
#define KTOT  (D_ + H_)  // 812
#define NCTA  128        // each CTA owns 4 h-columns -> 16 gate columns
#define NTHR  256
#define HC    4
#define GC    16
#define KP    256        // h panel depth (2 panels cover H=512)
#define ASTRIDE 260      // KP + 4 pad floats (bank-conflict-free LDS.128)

// Scratch (no cudaMalloc allowed)
__device__ float    g_h[2][B_ * H_];     // row-major [b][hcol], double-buffered
__device__ float    g_acc[B_];           // dense-layer partial accumulators
__device__ unsigned g_bar_count = 0;
__device__ unsigned g_bar_gen   = 0;

// ---- packed fp32 helpers (FFMA2: 2x fp32 FMA throughput, PTX-only) ----
__device__ __forceinline__ void ffma2(uint64_t& d, uint64_t a, uint64_t b) {
    asm volatile("fma.rn.f32x2 %0, %1, %2, %0;" : "+l"(d) : "l"(a), "l"(b));
}
__device__ __forceinline__ uint64_t pack_dup(float x) {
    uint64_t r; asm("mov.b64 %0, {%1, %1};" : "=l"(r) : "f"(x)); return r;
}
__device__ __forceinline__ uint64_t pack2(float x, float y) {
    uint64_t r; asm("mov.b64 %0, {%1, %2};" : "=l"(r) : "f"(x), "f"(y)); return r;
}
__device__ __forceinline__ float2 unpack2(uint64_t v) {
    float2 f; asm("mov.b64 {%0, %1}, %2;" : "=f"(f.x), "=f"(f.y) : "l"(v)); return f;
}
__device__ __forceinline__ void lds_v2u64(uint64_t& a, uint64_t& b, unsigned addr) {
    asm volatile("ld.shared.v2.u64 {%0, %1}, [%2];" : "=l"(a), "=l"(b) : "r"(addr));
}
// ---- scoped atomics for the CG-style grid barrier (no per-thread MEMBAR) ----
__device__ __forceinline__ unsigned atom_add_acqrel_gpu(unsigned* p, unsigned v) {
    unsigned r;
    asm volatile("atom.acq_rel.gpu.global.add.u32 %0, [%1], %2;"
                 : "=r"(r) : "l"(p), "r"(v) : "memory");
    return r;
}
__device__ __forceinline__ void atom_add_release_gpu(unsigned* p, unsigned v) {
    unsigned r;
    asm volatile("atom.release.gpu.global.add.u32 %0, [%1], %2;"
                 : "=r"(r) : "l"(p), "r"(v) : "memory");
}
__device__ __forceinline__ unsigned ld_acquire_gpu(const unsigned* p) {
    unsigned r;
    asm volatile("ld.acquire.gpu.global.u32 %0, [%1];" : "=r"(r) : "l"(p) : "memory");
    return r;
}
__device__ __forceinline__ void st_relaxed_gpu(unsigned* p, unsigned v) {
    asm volatile("st.relaxed.gpu.global.u32 [%0], %1;" :: "l"(p), "r"(v) : "memory");
}
__device__ __forceinline__ float sigm(float x)  { return 1.0f / (1.0f + __expf(-x)); }
__device__ __forceinline__ float tanh_f(float x){ return 2.0f * sigm(2.0f * x) - 1.0f; }

// Persistent LSTM scan. 128 CTAs, each owns 4 h-cols -> 16 gate cols.
// Thread map: m = w*8 + (lane&7) (batch row), ng = lane>>3 (gate 0..3).
extern __shared__ float smem_dyn[];
__global__ void __launch_bounds__(NTHR, 1)
lstm_scan_kernel(const float* __restrict__ essays,
                 const float* __restrict__ W_lstm,
                 const float* __restrict__ b_lstm,
                 const float* __restrict__ W_dense)
{
    float* Wsm  = smem_dyn;            // [KTOT][16]
    float* Apan = smem_dyn + KTOT*GC;  // [64][ASTRIDE] h panel / exchange buffer

    const int tid  = threadIdx.x;
    const int cc   = blockIdx.x;
    const int w    = tid >> 5;
    const int lane = tid & 31;
    const int m    = w*8 + (lane & 7);
    const int ng   = lane >> 3;
    const int q0   = ng*4;

    // Cache W slice: Wsm[k][q], col = (q>>2)*512 + cc*4 + (q&3)
    for (int idx = tid; idx < KTOT*GC; idx += NTHR) {
        int k = idx >> 4, q = idx & 15;
        int col = (q >> 2) * H_ + cc*HC + (q & 3);
        Wsm[idx] = W_lstm[(size_t)k * G_ + col];
    }

    const int colb = ng*H_ + cc*HC;
    const uint64_t bias01 = pack2(b_lstm[colb+0], b_lstm[colb+1]);
    const uint64_t bias23 = pack2(b_lstm[colb+2], b_lstm[colb+3]);

    const int hcol = cc*HC + ng;
    g_h[0][m*H_ + hcol] = 0.0f;               // h_{-1} = 0 (row-major)
    if (cc == 0 && tid < B_) g_acc[tid] = 0.0f;

    const unsigned wbase = (unsigned)__cvta_generic_to_shared(Wsm);

    __shared__ unsigned s_gen;
    if (tid == 0) s_gen = ld_acquire_gpu(&g_bar_gen);
    __syncthreads();
    const unsigned base = s_gen;

    // arrive #0 (zeroed h + g_acc published via release)
    if (tid == 0) {
        unsigned a = atom_add_acqrel_gpu(&g_bar_count, 1);
        if (a == NCTA-1) {
            st_relaxed_gpu(&g_bar_count, 0);
            atom_add_release_gpu(&g_bar_gen, 1);
        }
    }

    float    c_st = 0.0f, hsum = 0.0f;
    uint64_t acc01 = bias01, acc23 = bias23;

    const float* xrow = essays + (size_t)m * (T_ * D_);

    // X-phase: gates += x_t @ Wx (independent of h -> overlaps barrier skew)
    auto do_x = [&](int t) {
        const float4* xp = (const float4*)(xrow + (size_t)t * D_);
        #pragma unroll 3
        for (int kv = 0; kv < D_/4; kv++) {
            float4 a4 = xp[kv];
            unsigned wa = wbase + (unsigned)((kv*4)*GC + q0) * 4u;
            uint64_t w01, w23, a2;
            lds_v2u64(w01, w23, wa      ); a2 = pack_dup(a4.x); ffma2(acc01, w01, a2); ffma2(acc23, w23, a2);
            lds_v2u64(w01, w23, wa +  64); a2 = pack_dup(a4.y); ffma2(acc01, w01, a2); ffma2(acc23, w23, a2);
            lds_v2u64(w01, w23, wa + 128); a2 = pack_dup(a4.z); ffma2(acc01, w01, a2); ffma2(acc23, w23, a2);
            lds_v2u64(w01, w23, wa + 192); a2 = pack_dup(a4.w); ffma2(acc01, w01, a2); ffma2(acc23, w23, a2);
        }
    };

    do_x(0);

    const unsigned abase = (unsigned)__cvta_generic_to_shared(Apan);

    for (int t = 0; t < T_; t++) {
        // Wait for h_{t-1}: tid0 acquire-poll, then CTA barrier (cumulative)
        const unsigned target = base + (unsigned)(t + 1);
        if (tid == 0) {
            while ((int)(ld_acquire_gpu(&g_bar_gen) - target) < 0) { }
        }
        __syncthreads();

        // H-phase: gates += h_{t-1} @ Wh, staged in 2 panels of 256 k
        const float* hb = g_h[t & 1];
        #pragma unroll 1
        for (int p = 0; p < 2; p++) {
            const int kp = p * KP;
            // stage panel: global [m][512] -> SMEM [m][ASTRIDE], L2-direct
            const float4* src = (const float4*)hb;
            #pragma unroll
            for (int r = 0; r < 16; r++) {
                int idx = tid + r*NTHR;        // 4096 float4
                int mm = idx >> 6, kk = idx & 63;
                float4 v = __ldcg(src + (size_t)mm*(H_/4) + (kp/4) + kk);
                *(float4*)&Apan[mm*ASTRIDE + kk*4] = v;
            }
            __syncthreads();

            const unsigned wa0 = wbase + (unsigned)((D_ + kp)*GC + q0) * 4u;
            const float* arow = &Apan[m*ASTRIDE];
            #pragma unroll 4
            for (int k4 = 0; k4 < KP/4; k4++) {
                float4 a4 = *(const float4*)(arow + k4*4);
                unsigned wa = wa0 + (unsigned)k4 * 256u;
                uint64_t w01, w23, a2;
                lds_v2u64(w01, w23, wa      ); a2 = pack_dup(a4.x); ffma2(acc01, w01, a2); ffma2(acc23, w23, a2);
                lds_v2u64(w01, w23, wa +  64); a2 = pack_dup(a4.y); ffma2(acc01, w01, a2); ffma2(acc23, w23, a2);
                lds_v2u64(w01, w23, wa + 128); a2 = pack_dup(a4.z); ffma2(acc01, w01, a2); ffma2(acc23, w23, a2);
                lds_v2u64(w01, w23, wa + 192); a2 = pack_dup(a4.w); ffma2(acc01, w01, a2); ffma2(acc23, w23, a2);
            }
            __syncthreads();
        }

        // Gate exchange via SMEM (stride 65): thread owns (gate ng, cols jj=0..3),
        // needs (gates 0..3, col ng)
        float2 v01 = unpack2(acc01), v23 = unpack2(acc23);
        Apan[(q0+0)*65 + m] = v01.x;
        Apan[(q0+1)*65 + m] = v01.y;
        Apan[(q0+2)*65 + m] = v23.x;
        Apan[(q0+3)*65 + m] = v23.y;
        __syncthreads();
        float gi = Apan[(0*4 + ng)*65 + m];
        float gj = Apan[(1*4 + ng)*65 + m];
        float gf = Apan[(2*4 + ng)*65 + m];
        float go = Apan[(3*4 + ng)*65 + m];

        float nc = c_st * sigm(gf + 1.0f) + sigm(gi) * tanh_f(gj);
        float nh = tanh_f(nc) * sigm(go);
        c_st = nc;
        hsum += nh;
        g_h[(t+1) & 1][m*H_ + hcol] = nh;

        __syncthreads();   // all h stores issued + exchange reads done

        if (t < T_ - 1) {
            if (tid == 0) {
                unsigned a = atom_add_acqrel_gpu(&g_bar_count, 1);  // release: publishes h_t
                if (a == NCTA-1) {
                    st_relaxed_gpu(&g_bar_count, 0);
                    atom_add_release_gpu(&g_bar_gen, 1);
                }
            }
            acc01 = bias01; acc23 = bias23;
            do_x(t + 1);   // overlap next x-projection with barrier skew
        }
    }

    // Dense-layer partial: mot[m][hcol] * W_dense[hcol], reduce 4 ng lanes, atomicAdd
    float part = hsum * (1.0f / (float)T_) * W_dense[hcol];
    part += __shfl_xor_sync(0xffffffffu, part, 8);
    part += __shfl_xor_sync(0xffffffffu, part, 16);
    if (lane < 8) atomicAdd(&g_acc[m], part);
}

__global__ void finalize_kernel(const float* __restrict__ b_dense,
                                float* __restrict__ out)
{
    int b = threadIdx.x;  // 64 threads
    out[b] = 1.0f / (1.0f + expf(-(g_acc[b] + b_dense[0])));
}

extern "C" void kernel_launch(void* const* d_in, const int* in_sizes, int n_in,
                              void* d_out, int out_size)
{
    const float* essays  = (const float*)d_in[0];
    const float* W_lstm  = (const float*)d_in[1];
    const float* b_lstm  = (const float*)d_in[2];
    const float* W_dense = (const float*)d_in[3];
    const float* b_dense = (const float*)d_in[4];
    float* out = (float*)d_out;

    const int smem_bytes = (KTOT*GC + B_*ASTRIDE) * (int)sizeof(float); // 51968 + 66560 = 118528
    cudaFuncSetAttribute(lstm_scan_kernel,
                         cudaFuncAttributeMaxDynamicSharedMemorySize, smem_bytes);

    lstm_scan_kernel<<<NCTA, NTHR, smem_bytes>>>(essays, W_lstm, b_lstm, W_dense);
    finalize_kernel<<<1, B_>>>(b_dense, out);
}